// round 5
// baseline (speedup 1.0000x reference)
#include <cuda_runtime.h>

#define DIMC 768
#define HC 12
#define HDC 64
#define BC 4
#define LQC 2048
#define LKC 2048
#define NR (BC * LQC)   // 8192 rows for both queries and context

// ---------------- scratch (no allocations allowed) ----------------
__device__ float g_Q[BC * HC * LQC * HDC];   // (b,h,l,d)
__device__ float g_K[BC * HC * LKC * HDC];
__device__ float g_V[BC * HC * LKC * HDC];
__device__ float g_AO[BC * LQC * DIMC];      // attention output, (b,l,dim)

// =====================================================================
// Projection kernel: C[m, n] = sum_k A[m,k] * W[c0+n, k]  (64x64 tile =
// exactly one head's columns). MODE 1: fused per-head RMSNorm + RoPE
// epilogue; MODE 0: plain write (V projection).
// Output layout: (b, h, l, d) contiguous per (b,h).
// =====================================================================
template <int MODE>
__global__ void __launch_bounds__(256)
proj_head_kernel(const float* __restrict__ A,
                 const float* __restrict__ W,
                 int w_off,
                 const float* __restrict__ cosp,
                 const float* __restrict__ sinp,
                 const float* __restrict__ nw,
                 float* __restrict__ outp)
{
    __shared__ __align__(16) float As[16][64];
    __shared__ __align__(16) float Bs[16][64];
    __shared__ __align__(16) float Cs[64][68];
    __shared__ float rn[64];

    const int tid = threadIdx.x;
    const int ty = tid >> 4, tx = tid & 15;
    const int row0 = blockIdx.x * 64;
    const int head = blockIdx.y;
    const int c0 = w_off + head * 64;
    const int lr = tid >> 2;          // 0..63: row to load
    const int lk = (tid & 3) * 4;     // k sub-offset

    float acc[4][4] = {};

    for (int k0 = 0; k0 < DIMC; k0 += 16) {
        float4 av = *(const float4*)&A[(row0 + lr) * DIMC + k0 + lk];
        float4 bv = *(const float4*)&W[(c0 + lr) * DIMC + k0 + lk];
        As[lk + 0][lr] = av.x; As[lk + 1][lr] = av.y;
        As[lk + 2][lr] = av.z; As[lk + 3][lr] = av.w;
        Bs[lk + 0][lr] = bv.x; Bs[lk + 1][lr] = bv.y;
        Bs[lk + 2][lr] = bv.z; Bs[lk + 3][lr] = bv.w;
        __syncthreads();
#pragma unroll
        for (int kk = 0; kk < 16; kk++) {
            float4 a = *(const float4*)&As[kk][ty * 4];
            float4 b = *(const float4*)&Bs[kk][tx * 4];
            float ar[4] = {a.x, a.y, a.z, a.w};
            float br[4] = {b.x, b.y, b.z, b.w};
#pragma unroll
            for (int i = 0; i < 4; i++)
#pragma unroll
                for (int j = 0; j < 4; j++)
                    acc[i][j] += ar[i] * br[j];
        }
        __syncthreads();
    }

    // stage tile into smem for the per-head epilogue
#pragma unroll
    for (int i = 0; i < 4; i++) {
        float4 v = make_float4(acc[i][0], acc[i][1], acc[i][2], acc[i][3]);
        *(float4*)&Cs[ty * 4 + i][tx * 4] = v;
    }
    __syncthreads();

    if (MODE == 1) {
        if (tid < 64) {
            float s = 0.f;
#pragma unroll 8
            for (int c = 0; c < 64; c++) { float v = Cs[tid][c]; s += v * v; }
            rn[tid] = rsqrtf(s * (1.0f / 64.0f) + 1e-6f);
        }
        __syncthreads();
    }

    for (int e = tid; e < 4096; e += 256) {
        int row = e >> 6, d = e & 63;
        int grow = row0 + row;                 // global row in [0, 8192)
        int b = grow >> 11, l = grow & 2047;
        float* dst = outp + (((size_t)(b * HC + head) * LQC + l) << 6) + d;
        if (MODE == 1) {
            float nrm = rn[row];
            float v  = Cs[row][d] * nrm * nw[d];
            int dp = d ^ 32;
            float pv = Cs[row][dp] * nrm * nw[dp];
            float rh = (d < 32) ? -pv : pv;    // rotate_half
            float cv = cosp[(size_t)grow * 64 + d];
            float sv = sinp[(size_t)grow * 64 + d];
            *dst = v * cv + rh * sv;
        } else {
            *dst = Cs[row][d];
        }
    }
}

// =====================================================================
// Plain output GEMM: out[m, n] = sum_k AO[m,k] * Wo[n,k]
// =====================================================================
__global__ void __launch_bounds__(256)
gemm_out_kernel(const float* __restrict__ A,
                const float* __restrict__ W,
                float* __restrict__ outp)
{
    __shared__ __align__(16) float As[16][64];
    __shared__ __align__(16) float Bs[16][64];

    const int tid = threadIdx.x;
    const int ty = tid >> 4, tx = tid & 15;
    const int row0 = blockIdx.x * 64;
    const int c0 = blockIdx.y * 64;
    const int lr = tid >> 2;
    const int lk = (tid & 3) * 4;

    float acc[4][4] = {};

    for (int k0 = 0; k0 < DIMC; k0 += 16) {
        float4 av = *(const float4*)&A[(row0 + lr) * DIMC + k0 + lk];
        float4 bv = *(const float4*)&W[(c0 + lr) * DIMC + k0 + lk];
        As[lk + 0][lr] = av.x; As[lk + 1][lr] = av.y;
        As[lk + 2][lr] = av.z; As[lk + 3][lr] = av.w;
        Bs[lk + 0][lr] = bv.x; Bs[lk + 1][lr] = bv.y;
        Bs[lk + 2][lr] = bv.z; Bs[lk + 3][lr] = bv.w;
        __syncthreads();
#pragma unroll
        for (int kk = 0; kk < 16; kk++) {
            float4 a = *(const float4*)&As[kk][ty * 4];
            float4 b = *(const float4*)&Bs[kk][tx * 4];
            float ar[4] = {a.x, a.y, a.z, a.w};
            float br[4] = {b.x, b.y, b.z, b.w};
#pragma unroll
            for (int i = 0; i < 4; i++)
#pragma unroll
                for (int j = 0; j < 4; j++)
                    acc[i][j] += ar[i] * br[j];
        }
        __syncthreads();
    }

#pragma unroll
    for (int i = 0; i < 4; i++) {
        float4 v = make_float4(acc[i][0], acc[i][1], acc[i][2], acc[i][3]);
        *(float4*)&outp[(size_t)(row0 + ty * 4 + i) * DIMC + c0 + tx * 4] = v;
    }
}

// =====================================================================
// Flash attention (fp32, online softmax). One CTA = 64 q rows of one
// (b,h) pair. Softmax scale folded into Q at load.
// smem: Qs, Ks, Vs, Ps each 64x68 floats -> 69632 B dynamic.
// =====================================================================
#define FA_SMEM (4 * 64 * 68 * 4)

__global__ void __launch_bounds__(256)
flash_kernel(const float* __restrict__ gQ,
             const float* __restrict__ gK,
             const float* __restrict__ gV,
             float* __restrict__ gAO)
{
    extern __shared__ __align__(16) float sm[];
    float* Qs = sm;
    float* Ks = sm + 64 * 68;
    float* Vs = sm + 2 * 64 * 68;
    float* Ps = sm + 3 * 64 * 68;

    const int tid = threadIdx.x;
    const int ty = tid >> 4, tx = tid & 15;
    const int bh = blockIdx.y;
    const int q0 = blockIdx.x * 64;

    const float* Qb = gQ + (size_t)bh * LQC * HDC;
    const float* Kb = gK + (size_t)bh * LKC * HDC;
    const float* Vb = gV + (size_t)bh * LKC * HDC;

    // load Q tile, pre-scaled by 1/sqrt(HD) = 0.125
    for (int e = tid; e < 1024; e += 256) {
        int row = e >> 4, d = (e & 15) * 4;
        float4 v = *(const float4*)&Qb[(size_t)(q0 + row) * 64 + d];
        v.x *= 0.125f; v.y *= 0.125f; v.z *= 0.125f; v.w *= 0.125f;
        *(float4*)&Qs[row * 68 + d] = v;
    }

    float accO[4][4] = {};
    float m[4] = {-1e30f, -1e30f, -1e30f, -1e30f};
    float l[4] = {};

    for (int k0 = 0; k0 < LKC; k0 += 64) {
        for (int e = tid; e < 1024; e += 256) {
            int row = e >> 4, d = (e & 15) * 4;
            *(float4*)&Ks[row * 68 + d] = *(const float4*)&Kb[(size_t)(k0 + row) * 64 + d];
            *(float4*)&Vs[row * 68 + d] = *(const float4*)&Vb[(size_t)(k0 + row) * 64 + d];
        }
        __syncthreads();

        // S = Q * K^T (scaled): 64x64x64
        float accS[4][4] = {};
#pragma unroll
        for (int d4 = 0; d4 < 16; d4++) {
            float qa[4][4], kb[4][4];
#pragma unroll
            for (int i = 0; i < 4; i++) {
                float4 t = *(const float4*)&Qs[(ty * 4 + i) * 68 + d4 * 4];
                qa[i][0] = t.x; qa[i][1] = t.y; qa[i][2] = t.z; qa[i][3] = t.w;
            }
#pragma unroll
            for (int j = 0; j < 4; j++) {
                float4 t = *(const float4*)&Ks[(tx * 4 + j) * 68 + d4 * 4];
                kb[j][0] = t.x; kb[j][1] = t.y; kb[j][2] = t.z; kb[j][3] = t.w;
            }
#pragma unroll
            for (int i = 0; i < 4; i++)
#pragma unroll
                for (int j = 0; j < 4; j++)
#pragma unroll
                    for (int dd = 0; dd < 4; dd++)
                        accS[i][j] += qa[i][dd] * kb[j][dd];
        }

        // online softmax over rows (16 lanes per row-group share a row set)
#pragma unroll
        for (int i = 0; i < 4; i++) {
            float mx = fmaxf(fmaxf(accS[i][0], accS[i][1]),
                             fmaxf(accS[i][2], accS[i][3]));
#pragma unroll
            for (int o = 8; o >= 1; o >>= 1)
                mx = fmaxf(mx, __shfl_xor_sync(0xffffffffu, mx, o));
            float mn = fmaxf(m[i], mx);
            float al = __expf(m[i] - mn);
            float rs = 0.f;
#pragma unroll
            for (int j = 0; j < 4; j++) {
                float p = __expf(accS[i][j] - mn);
                accS[i][j] = p;
                rs += p;
            }
#pragma unroll
            for (int o = 8; o >= 1; o >>= 1)
                rs += __shfl_xor_sync(0xffffffffu, rs, o);
            l[i] = l[i] * al + rs;
            m[i] = mn;
#pragma unroll
            for (int j = 0; j < 4; j++) accO[i][j] *= al;
            *(float4*)&Ps[(ty * 4 + i) * 68 + tx * 4] =
                make_float4(accS[i][0], accS[i][1], accS[i][2], accS[i][3]);
        }
        __syncthreads();

        // O += P * V : 64x64x64
#pragma unroll
        for (int k4 = 0; k4 < 16; k4++) {
            float pa[4][4], vv[4][4];
#pragma unroll
            for (int i = 0; i < 4; i++) {
                float4 t = *(const float4*)&Ps[(ty * 4 + i) * 68 + k4 * 4];
                pa[i][0] = t.x; pa[i][1] = t.y; pa[i][2] = t.z; pa[i][3] = t.w;
            }
#pragma unroll
            for (int kk = 0; kk < 4; kk++) {
                float4 t = *(const float4*)&Vs[(k4 * 4 + kk) * 68 + tx * 4];
                vv[kk][0] = t.x; vv[kk][1] = t.y; vv[kk][2] = t.z; vv[kk][3] = t.w;
            }
#pragma unroll
            for (int i = 0; i < 4; i++)
#pragma unroll
                for (int j = 0; j < 4; j++)
#pragma unroll
                    for (int kk = 0; kk < 4; kk++)
                        accO[i][j] += pa[i][kk] * vv[kk][j];
        }
        __syncthreads();
    }

    const int b = bh / HC, h = bh % HC;
#pragma unroll
    for (int i = 0; i < 4; i++) {
        float inv = 1.0f / l[i];
        float4 v = make_float4(accO[i][0] * inv, accO[i][1] * inv,
                               accO[i][2] * inv, accO[i][3] * inv);
        *(float4*)&gAO[(size_t)(b * LQC + q0 + ty * 4 + i) * DIMC + h * 64 + tx * 4] = v;
    }
}

// =====================================================================
// launch
// =====================================================================
extern "C" void kernel_launch(void* const* d_in, const int* in_sizes, int n_in,
                              void* d_out, int out_size)
{
    const float* queries = (const float*)d_in[0];
    const float* context = (const float*)d_in[1];
    const float* qcos    = (const float*)d_in[2];
    const float* qsin    = (const float*)d_in[3];
    const float* kcos    = (const float*)d_in[4];
    const float* ksin    = (const float*)d_in[5];
    const float* Wq      = (const float*)d_in[6];
    const float* Wkv     = (const float*)d_in[7];
    const float* Wo      = (const float*)d_in[8];
    const float* qnw     = (const float*)d_in[9];
    const float* knw     = (const float*)d_in[10];
    float* out = (float*)d_out;

    float *pQ, *pK, *pV, *pAO;
    cudaGetSymbolAddress((void**)&pQ,  g_Q);
    cudaGetSymbolAddress((void**)&pK,  g_K);
    cudaGetSymbolAddress((void**)&pV,  g_V);
    cudaGetSymbolAddress((void**)&pAO, g_AO);

    dim3 blk(256);
    dim3 gproj(NR / 64, HC);

    // Q / K projections with fused RMSNorm + RoPE; V plain
    proj_head_kernel<1><<<gproj, blk>>>(queries, Wq,  0,    qcos, qsin, qnw, pQ);
    proj_head_kernel<1><<<gproj, blk>>>(context, Wkv, 0,    kcos, ksin, knw, pK);
    proj_head_kernel<0><<<gproj, blk>>>(context, Wkv, DIMC, qcos, qsin, qnw, pV);

    cudaFuncSetAttribute(flash_kernel,
                         cudaFuncAttributeMaxDynamicSharedMemorySize, FA_SMEM);
    flash_kernel<<<dim3(LQC / 64, BC * HC), blk, FA_SMEM>>>(pQ, pK, pV, pAO);

    gemm_out_kernel<<<dim3(NR / 64, DIMC / 64), blk>>>(pAO, Wo, out);
}

// round 8
// speedup vs baseline: 1.9518x; 1.9518x over previous
#include <cuda_runtime.h>
#include <cuda_bf16.h>
#include <cstdint>
#include <cstddef>

#define DIMC 768
#define HC 12
#define HDC 64
#define BC 4
#define LQC 2048
#define LKC 2048
#define NR (BC * LQC)   // 8192 rows

// ---------------- scratch (no allocations allowed) ----------------
__device__ float g_Q[BC * HC * LQC * HDC];   // (b,h,l,d) fp32
__device__ float g_K[BC * HC * LKC * HDC];
__device__ float g_V[BC * HC * LKC * HDC];
__device__ float g_AO[BC * LQC * DIMC];      // (b,l,dim) fp32

// =====================================================================
// mma.sync helpers (compute_100-safe: sm_80-era PTX, runs on Blackwell
// legacy tensor-core path; tcgen05 is NOT available at this PTX target)
// =====================================================================
__device__ __forceinline__ uint32_t smem_u32(const void* p) {
    uint32_t a;
    asm("{ .reg .u64 t; cvta.to.shared.u64 t, %1; cvt.u32.u64 %0, t; }"
        : "=r"(a) : "l"(p));
    return a;
}
__device__ __forceinline__ void ldmx4(uint32_t* r, uint32_t a) {
    asm volatile("ldmatrix.sync.aligned.m8n8.x4.shared.b16 {%0,%1,%2,%3}, [%4];"
                 : "=r"(r[0]), "=r"(r[1]), "=r"(r[2]), "=r"(r[3]) : "r"(a));
}
__device__ __forceinline__ void ldmx2(uint32_t* r, uint32_t a) {
    asm volatile("ldmatrix.sync.aligned.m8n8.x2.shared.b16 {%0,%1}, [%2];"
                 : "=r"(r[0]), "=r"(r[1]) : "r"(a));
}
__device__ __forceinline__ void mma_bf16(float* c, const uint32_t* a,
                                         const uint32_t* b) {
    asm volatile(
        "mma.sync.aligned.m16n8k16.row.col.f32.bf16.bf16.f32 "
        "{%0,%1,%2,%3}, {%4,%5,%6,%7}, {%8,%9}, {%0,%1,%2,%3};"
        : "+f"(c[0]), "+f"(c[1]), "+f"(c[2]), "+f"(c[3])
        : "r"(a[0]), "r"(a[1]), "r"(a[2]), "r"(a[3]), "r"(b[0]), "r"(b[1]));
}
// float -> (hi, lo) bf16 split, packed pairwise
__device__ __forceinline__ void split2(float x, float y, uint32_t& h, uint32_t& l) {
    __nv_bfloat16 hx = __float2bfloat16(x);
    __nv_bfloat16 hy = __float2bfloat16(y);
    __nv_bfloat16 lx = __float2bfloat16(x - __bfloat162float(hx));
    __nv_bfloat16 ly = __float2bfloat16(y - __bfloat162float(hy));
    h = (uint32_t)__bfloat16_as_ushort(hx) | ((uint32_t)__bfloat16_as_ushort(hy) << 16);
    l = (uint32_t)__bfloat16_as_ushort(lx) | ((uint32_t)__bfloat16_as_ushort(ly) << 16);
}

// =====================================================================
// mma.sync split-bf16 GEMM: C[128,64] tile (row0, head) of
//   C[m,n] = sum_k A[m,k] * W[c0+n, k],  c0 = w_off + head*64
// MODE 0: write (b,h,l,d)                       (V projection)
// MODE 1: RMSNorm + RoPE epilogue -> (b,h,l,d)  (Q/K projections)
// MODE 2: write row-major [8192,768] col head*64 (output projection)
//
// smem layout (dynamic, bytes):
//   Ah [128][72] bf16   @ 0       (18432)
//   Al [128][72] bf16   @ 18432
//   Bh [ 64][72] bf16   @ 36864   (9216)
//   Bl [ 64][72] bf16   @ 46080
//   rn [128] f32        @ 55296
//   Cs [128][68] f32 reuses @0 after mainloop (34816 <= 36864)
// =====================================================================
#define AH_OFF 0
#define AL_OFF 18432
#define BH_OFF 36864
#define BL_OFF 46080
#define RN_OFF 55296
#define SMEM_MM (55296 + 512)

template <int MODE>
__global__ void __launch_bounds__(256)
mma_gemm(const float* __restrict__ Ag, const float* __restrict__ Wg,
         int w_off,
         const float* __restrict__ cosp, const float* __restrict__ sinp,
         const float* __restrict__ nw, float* __restrict__ outp)
{
    extern __shared__ __align__(16) char sm[];
    const int tid = threadIdx.x;
    const int w = tid >> 5, lane = tid & 31;
    const int row0 = blockIdx.x * 128;
    const int head = blockIdx.y;
    const int c0 = w_off + head * 64;

    float acc[8][4] = {};   // 8 n-tiles (n8) x 4 f32 per m16n8 frag

    // per-thread ldmatrix addresses (k-step offset added in loop)
    const uint32_t sb = smem_u32(sm);
    const uint32_t a_row = (uint32_t)(w * 16 + (lane & 15));
    const uint32_t a_koff = (uint32_t)((lane >> 4) * 8);
    const uint32_t ah_base = sb + AH_OFF + (a_row * 72 + a_koff) * 2;
    const uint32_t al_base = sb + AL_OFF + (a_row * 72 + a_koff) * 2;
    const uint32_t b_row = (uint32_t)(lane & 7);
    const uint32_t b_koff = (uint32_t)(((lane >> 3) & 1) * 8);

    for (int kc = 0; kc < 12; kc++) {
        // ---- load + split A chunk: 128 rows x 64 cols fp32 ----
        for (int e = tid; e < 2048; e += 256) {
            int r = e >> 4, c4 = e & 15;
            float4 v = *(const float4*)&Ag[(size_t)(row0 + r) * DIMC + kc * 64 + c4 * 4];
            uint32_t h0, l0, h1, l1;
            split2(v.x, v.y, h0, l0);
            split2(v.z, v.w, h1, l1);
            uint32_t off = (uint32_t)(r * 72 + c4 * 4) * 2;
            *(uint2*)(sm + AH_OFF + off) = make_uint2(h0, h1);
            *(uint2*)(sm + AL_OFF + off) = make_uint2(l0, l1);
        }
        // ---- load + split B chunk: 64 rows x 64 cols fp32 ----
        for (int e = tid; e < 1024; e += 256) {
            int r = e >> 4, c4 = e & 15;
            float4 v = *(const float4*)&Wg[(size_t)(c0 + r) * DIMC + kc * 64 + c4 * 4];
            uint32_t h0, l0, h1, l1;
            split2(v.x, v.y, h0, l0);
            split2(v.z, v.w, h1, l1);
            uint32_t off = (uint32_t)(r * 72 + c4 * 4) * 2;
            *(uint2*)(sm + BH_OFF + off) = make_uint2(h0, h1);
            *(uint2*)(sm + BL_OFF + off) = make_uint2(l0, l1);
        }
        __syncthreads();

        // ---- 4 k16 steps ----
#pragma unroll
        for (int s = 0; s < 4; s++) {
            uint32_t ah[4], al[4];
            ldmx4(ah, ah_base + (uint32_t)(s * 16) * 2);
            ldmx4(al, al_base + (uint32_t)(s * 16) * 2);
#pragma unroll
            for (int j = 0; j < 8; j++) {
                uint32_t boff = ((uint32_t)(j * 8) + b_row) * 144 +
                                ((uint32_t)(s * 16) + b_koff) * 2;
                uint32_t bh[2], bl[2];
                ldmx2(bh, sb + BH_OFF + boff);
                ldmx2(bl, sb + BL_OFF + boff);
                mma_bf16(acc[j], ah, bh);
                mma_bf16(acc[j], ah, bl);
                mma_bf16(acc[j], al, bh);
            }
        }
        __syncthreads();
    }

    // ---- stage C to smem (reuse Ah/Al region) ----
    float* Cs = (float*)(sm + AH_OFF);     // [128][68]
    const int g = lane >> 2, tg = lane & 3;
#pragma unroll
    for (int j = 0; j < 8; j++) {
        Cs[(w * 16 + g) * 68 + j * 8 + tg * 2 + 0] = acc[j][0];
        Cs[(w * 16 + g) * 68 + j * 8 + tg * 2 + 1] = acc[j][1];
        Cs[(w * 16 + g + 8) * 68 + j * 8 + tg * 2 + 0] = acc[j][2];
        Cs[(w * 16 + g + 8) * 68 + j * 8 + tg * 2 + 1] = acc[j][3];
    }
    __syncthreads();

    float* rnp = (float*)(sm + RN_OFF);
    if (MODE == 1) {
        if (tid < 128) {
            float s = 0.f;
#pragma unroll 8
            for (int c = 0; c < 64; c++) { float v = Cs[tid * 68 + c]; s += v * v; }
            rnp[tid] = rsqrtf(s * (1.0f / 64.0f) + 1e-6f);
        }
        __syncthreads();
    }

    for (int e = tid; e < 8192; e += 256) {
        int r = e >> 6, d = e & 63;
        int grow = row0 + r;
        if (MODE == 1) {
            int b = grow >> 11, l = grow & 2047;
            float nrm = rnp[r];
            float v = Cs[r * 68 + d] * nrm * nw[d];
            int dp = d ^ 32;
            float pv = Cs[r * 68 + dp] * nrm * nw[dp];
            float rh = (d < 32) ? -pv : pv;
            float cv = cosp[(size_t)grow * 64 + d];
            float sv = sinp[(size_t)grow * 64 + d];
            outp[(((size_t)(b * HC + head) * LQC + l) << 6) + d] = v * cv + rh * sv;
        } else if (MODE == 0) {
            int b = grow >> 11, l = grow & 2047;
            outp[(((size_t)(b * HC + head) * LQC + l) << 6) + d] = Cs[r * 68 + d];
        } else {
            outp[(size_t)grow * DIMC + head * 64 + d] = Cs[r * 68 + d];
        }
    }
}

// =====================================================================
// Flash attention: 128 q x 128 kv tile, 8x8 microtile, XOR-swizzled
// smem for conflict-free float4 access with 8-row-strided fragments.
// smem: Qs/Ks/Vs 128x16 float4 (32KB each) + Pt 128x32 float4 (64KB).
// =====================================================================
#define FA_SMEM (10240 * 16)

__global__ void __launch_bounds__(256, 1)
flash_kernel(const float* __restrict__ gQ,
             const float* __restrict__ gK,
             const float* __restrict__ gV,
             float* __restrict__ gAO)
{
    extern __shared__ __align__(16) float4 fa_sm[];
    float4* Qs = fa_sm;           // [128][16]
    float4* Ks = fa_sm + 2048;
    float4* Vs = fa_sm + 4096;
    float4* Pt = fa_sm + 6144;    // [128][32]  (P transposed: [k][q])

    const int tid = threadIdx.x;
    const int tx = tid & 15, ty = tid >> 4;
    const int bh = blockIdx.y;
    const int q0 = blockIdx.x * 128;

    const float4* Qb = (const float4*)(gQ + (size_t)bh * LQC * HDC);
    const float4* Kb = (const float4*)(gK + (size_t)bh * LKC * HDC);
    const float4* Vb = (const float4*)(gV + (size_t)bh * LKC * HDC);

    // load Q tile with scale 1/8, XOR-swizzled
    for (int e = tid; e < 2048; e += 256) {
        int r = e >> 4, c = e & 15;
        float4 v = Qb[(size_t)(q0 + r) * 16 + c];
        v.x *= 0.125f; v.y *= 0.125f; v.z *= 0.125f; v.w *= 0.125f;
        Qs[r * 16 + (c ^ ((r >> 3) & 15))] = v;
    }

    float accO[8][4] = {};
    float m[8], l[8] = {};
#pragma unroll
    for (int i = 0; i < 8; i++) m[i] = -1e30f;

    for (int k0 = 0; k0 < LKC; k0 += 128) {
        for (int e = tid; e < 2048; e += 256) {
            int r = e >> 4, c = e & 15;
            int p = r * 16 + (c ^ ((r >> 3) & 15));
            Ks[p] = Kb[(size_t)(k0 + r) * 16 + c];
            Vs[p] = Vb[(size_t)(k0 + r) * 16 + c];
        }
        __syncthreads();

        // S = Q K^T : thread = 8 q-rows (ty) x 8 kv-cols (tx)
        float accS[8][8] = {};
#pragma unroll 4
        for (int k4 = 0; k4 < 16; k4++) {
            float4 qa[8];
#pragma unroll
            for (int i = 0; i < 8; i++)
                qa[i] = Qs[(ty * 8 + i) * 16 + (k4 ^ ty)];
#pragma unroll
            for (int j = 0; j < 8; j++) {
                float4 kb = Ks[(tx * 8 + j) * 16 + (k4 ^ tx)];
#pragma unroll
                for (int i = 0; i < 8; i++)
                    accS[i][j] += qa[i].x * kb.x + qa[i].y * kb.y
                                + qa[i].z * kb.z + qa[i].w * kb.w;
            }
        }

        // online softmax (row split over the 16-lane tx group)
#pragma unroll
        for (int i = 0; i < 8; i++) {
            float mx = accS[i][0];
#pragma unroll
            for (int j = 1; j < 8; j++) mx = fmaxf(mx, accS[i][j]);
#pragma unroll
            for (int o = 8; o >= 1; o >>= 1)
                mx = fmaxf(mx, __shfl_xor_sync(0xffffffffu, mx, o));
            float mn = fmaxf(m[i], mx);
            float al = __expf(m[i] - mn);
            float rs = 0.f;
#pragma unroll
            for (int j = 0; j < 8; j++) {
                float p = __expf(accS[i][j] - mn);
                accS[i][j] = p; rs += p;
            }
#pragma unroll
            for (int o = 8; o >= 1; o >>= 1)
                rs += __shfl_xor_sync(0xffffffffu, rs, o);
            l[i] = l[i] * al + rs;
            m[i] = mn;
            accO[i][0] *= al; accO[i][1] *= al;
            accO[i][2] *= al; accO[i][3] *= al;
        }

        // write P^T (rows = kv index, swizzle key = tx)
#pragma unroll
        for (int jj = 0; jj < 8; jj++) {
            int j = tx * 8 + jj;
            Pt[j * 32 + ((ty * 2)     ^ tx)] =
                make_float4(accS[0][jj], accS[1][jj], accS[2][jj], accS[3][jj]);
            Pt[j * 32 + ((ty * 2 + 1) ^ tx)] =
                make_float4(accS[4][jj], accS[5][jj], accS[6][jj], accS[7][jj]);
        }
        __syncthreads();

        // O += P V : thread = 8 q-rows (ty) x 4 d-cols (tx)
#pragma unroll 8
        for (int kk = 0; kk < 128; kk++) {
            int key = (kk >> 3) & 15;
            float4 p0 = Pt[kk * 32 + ((ty * 2)     ^ key)];
            float4 p1 = Pt[kk * 32 + ((ty * 2 + 1) ^ key)];
            float4 vv = Vs[kk * 16 + (tx ^ key)];
            float pr[8] = {p0.x, p0.y, p0.z, p0.w, p1.x, p1.y, p1.z, p1.w};
#pragma unroll
            for (int i = 0; i < 8; i++) {
                accO[i][0] += pr[i] * vv.x; accO[i][1] += pr[i] * vv.y;
                accO[i][2] += pr[i] * vv.z; accO[i][3] += pr[i] * vv.w;
            }
        }
        __syncthreads();
    }

    const int b = bh / HC, h = bh % HC;
#pragma unroll
    for (int i = 0; i < 8; i++) {
        float inv = 1.0f / l[i];
        float4 o = make_float4(accO[i][0] * inv, accO[i][1] * inv,
                               accO[i][2] * inv, accO[i][3] * inv);
        *(float4*)&gAO[(size_t)(b * LQC + q0 + ty * 8 + i) * DIMC + h * 64 + tx * 4] = o;
    }
}

// =====================================================================
// launch
// =====================================================================
extern "C" void kernel_launch(void* const* d_in, const int* in_sizes, int n_in,
                              void* d_out, int out_size)
{
    const float* queries = (const float*)d_in[0];
    const float* context = (const float*)d_in[1];
    const float* qcos    = (const float*)d_in[2];
    const float* qsin    = (const float*)d_in[3];
    const float* kcos    = (const float*)d_in[4];
    const float* ksin    = (const float*)d_in[5];
    const float* Wq      = (const float*)d_in[6];
    const float* Wkv     = (const float*)d_in[7];
    const float* Wo      = (const float*)d_in[8];
    const float* qnw     = (const float*)d_in[9];
    const float* knw     = (const float*)d_in[10];
    float* out = (float*)d_out;

    float *pQ, *pK, *pV, *pAO;
    cudaGetSymbolAddress((void**)&pQ,  g_Q);
    cudaGetSymbolAddress((void**)&pK,  g_K);
    cudaGetSymbolAddress((void**)&pV,  g_V);
    cudaGetSymbolAddress((void**)&pAO, g_AO);

    cudaFuncSetAttribute(mma_gemm<0>, cudaFuncAttributeMaxDynamicSharedMemorySize, SMEM_MM);
    cudaFuncSetAttribute(mma_gemm<1>, cudaFuncAttributeMaxDynamicSharedMemorySize, SMEM_MM);
    cudaFuncSetAttribute(mma_gemm<2>, cudaFuncAttributeMaxDynamicSharedMemorySize, SMEM_MM);
    cudaFuncSetAttribute(flash_kernel, cudaFuncAttributeMaxDynamicSharedMemorySize, FA_SMEM);

    dim3 blk(256);
    dim3 gg(NR / 128, HC);

    mma_gemm<1><<<gg, blk, SMEM_MM>>>(queries, Wq,  0,    qcos, qsin, qnw, pQ);
    mma_gemm<1><<<gg, blk, SMEM_MM>>>(context, Wkv, 0,    kcos, ksin, knw, pK);
    mma_gemm<0><<<gg, blk, SMEM_MM>>>(context, Wkv, DIMC,
                                      (const float*)0, (const float*)0,
                                      (const float*)0, pV);

    flash_kernel<<<dim3(LQC / 128, BC * HC), blk, FA_SMEM>>>(pQ, pK, pV, pAO);

    mma_gemm<2><<<gg, blk, SMEM_MM>>>(pAO, Wo, 0,
                                      (const float*)0, (const float*)0,
                                      (const float*)0, out);
}

// round 9
// speedup vs baseline: 2.8012x; 1.4352x over previous
#include <cuda_runtime.h>
#include <cuda_bf16.h>
#include <cstdint>
#include <cstddef>

#define DIMC 768
#define HC 12
#define HDC 64
#define BC 4
#define LQC 2048
#define LKC 2048
#define NR (BC * LQC)   // 8192 rows

// ---------------- scratch (no allocations allowed) ----------------
__device__ float g_Q[BC * HC * LQC * HDC];   // (b,h,l,d) fp32
__device__ float g_K[BC * HC * LKC * HDC];
__device__ float g_V[BC * HC * LKC * HDC];
__device__ float g_AO[BC * LQC * DIMC];      // (b,l,dim) fp32

// =====================================================================
// mma.sync helpers (compute_100-safe legacy tensor-core path)
// =====================================================================
__device__ __forceinline__ uint32_t smem_u32(const void* p) {
    uint32_t a;
    asm("{ .reg .u64 t; cvta.to.shared.u64 t, %1; cvt.u32.u64 %0, t; }"
        : "=r"(a) : "l"(p));
    return a;
}
__device__ __forceinline__ void ldmx4(uint32_t* r, uint32_t a) {
    asm volatile("ldmatrix.sync.aligned.m8n8.x4.shared.b16 {%0,%1,%2,%3}, [%4];"
                 : "=r"(r[0]), "=r"(r[1]), "=r"(r[2]), "=r"(r[3]) : "r"(a));
}
__device__ __forceinline__ void ldmx2(uint32_t* r, uint32_t a) {
    asm volatile("ldmatrix.sync.aligned.m8n8.x2.shared.b16 {%0,%1}, [%2];"
                 : "=r"(r[0]), "=r"(r[1]) : "r"(a));
}
__device__ __forceinline__ void ldmx2t(uint32_t* r, uint32_t a) {
    asm volatile("ldmatrix.sync.aligned.m8n8.x2.trans.shared.b16 {%0,%1}, [%2];"
                 : "=r"(r[0]), "=r"(r[1]) : "r"(a));
}
__device__ __forceinline__ void mma_bf16(float* c, const uint32_t* a,
                                         const uint32_t* b) {
    asm volatile(
        "mma.sync.aligned.m16n8k16.row.col.f32.bf16.bf16.f32 "
        "{%0,%1,%2,%3}, {%4,%5,%6,%7}, {%8,%9}, {%0,%1,%2,%3};"
        : "+f"(c[0]), "+f"(c[1]), "+f"(c[2]), "+f"(c[3])
        : "r"(a[0]), "r"(a[1]), "r"(a[2]), "r"(a[3]), "r"(b[0]), "r"(b[1]));
}
// float -> (hi, lo) bf16 split, packed pairwise
__device__ __forceinline__ void split2(float x, float y, uint32_t& h, uint32_t& l) {
    __nv_bfloat16 hx = __float2bfloat16(x);
    __nv_bfloat16 hy = __float2bfloat16(y);
    __nv_bfloat16 lx = __float2bfloat16(x - __bfloat162float(hx));
    __nv_bfloat16 ly = __float2bfloat16(y - __bfloat162float(hy));
    h = (uint32_t)__bfloat16_as_ushort(hx) | ((uint32_t)__bfloat16_as_ushort(hy) << 16);
    l = (uint32_t)__bfloat16_as_ushort(lx) | ((uint32_t)__bfloat16_as_ushort(ly) << 16);
}
// FMA-pipe exp2 (no MUFU): magic-number round + deg-5 Taylor + exponent splice.
// Valid for t <= ~80; clamps below -126 (result ~0). rel err ~2e-6.
__device__ __forceinline__ float fexp2(float t) {
    t = fmaxf(t, -126.0f);
    float r = t + 12582912.0f;             // 1.5 * 2^23
    int32_t ib = __float_as_int(r);        // low bits hold round(t)
    float nf = r - 12582912.0f;
    float f = t - nf;                      // f in [-0.5, 0.5]
    float p = 0.00133336f;
    p = fmaf(p, f, 0.00961813f);
    p = fmaf(p, f, 0.05550411f);
    p = fmaf(p, f, 0.24022651f);
    p = fmaf(p, f, 0.69314718f);
    p = fmaf(p, f, 1.0f);
    return __int_as_float(__float_as_int(p) + (ib << 23));
}
#define L2E 1.4426950408889634f

// =====================================================================
// mma.sync split-bf16 GEMM (unchanged from R8 — verified at 9e-6):
// C[128,64] tile of C[m,n] = sum_k A[m,k] * W[c0+n,k]
// MODE 0: V proj -> (b,h,l,d); MODE 1: +RMSNorm+RoPE; MODE 2: Wo proj
// =====================================================================
#define AH_OFF 0
#define AL_OFF 18432
#define BH_OFF 36864
#define BL_OFF 46080
#define RN_OFF 55296
#define SMEM_MM (55296 + 512)

template <int MODE>
__global__ void __launch_bounds__(256)
mma_gemm(const float* __restrict__ Ag, const float* __restrict__ Wg,
         int w_off,
         const float* __restrict__ cosp, const float* __restrict__ sinp,
         const float* __restrict__ nw, float* __restrict__ outp)
{
    extern __shared__ __align__(16) char sm[];
    const int tid = threadIdx.x;
    const int w = tid >> 5, lane = tid & 31;
    const int row0 = blockIdx.x * 128;
    const int head = blockIdx.y;
    const int c0 = w_off + head * 64;

    float acc[8][4] = {};

    const uint32_t sb = smem_u32(sm);
    const uint32_t a_row = (uint32_t)(w * 16 + (lane & 15));
    const uint32_t a_koff = (uint32_t)((lane >> 4) * 8);
    const uint32_t ah_base = sb + AH_OFF + (a_row * 72 + a_koff) * 2;
    const uint32_t al_base = sb + AL_OFF + (a_row * 72 + a_koff) * 2;
    const uint32_t b_row = (uint32_t)(lane & 7);
    const uint32_t b_koff = (uint32_t)(((lane >> 3) & 1) * 8);

    for (int kc = 0; kc < 12; kc++) {
        for (int e = tid; e < 2048; e += 256) {
            int r = e >> 4, c4 = e & 15;
            float4 v = *(const float4*)&Ag[(size_t)(row0 + r) * DIMC + kc * 64 + c4 * 4];
            uint32_t h0, l0, h1, l1;
            split2(v.x, v.y, h0, l0);
            split2(v.z, v.w, h1, l1);
            uint32_t off = (uint32_t)(r * 72 + c4 * 4) * 2;
            *(uint2*)(sm + AH_OFF + off) = make_uint2(h0, h1);
            *(uint2*)(sm + AL_OFF + off) = make_uint2(l0, l1);
        }
        for (int e = tid; e < 1024; e += 256) {
            int r = e >> 4, c4 = e & 15;
            float4 v = *(const float4*)&Wg[(size_t)(c0 + r) * DIMC + kc * 64 + c4 * 4];
            uint32_t h0, l0, h1, l1;
            split2(v.x, v.y, h0, l0);
            split2(v.z, v.w, h1, l1);
            uint32_t off = (uint32_t)(r * 72 + c4 * 4) * 2;
            *(uint2*)(sm + BH_OFF + off) = make_uint2(h0, h1);
            *(uint2*)(sm + BL_OFF + off) = make_uint2(l0, l1);
        }
        __syncthreads();

#pragma unroll
        for (int s = 0; s < 4; s++) {
            uint32_t ah[4], al[4];
            ldmx4(ah, ah_base + (uint32_t)(s * 16) * 2);
            ldmx4(al, al_base + (uint32_t)(s * 16) * 2);
#pragma unroll
            for (int j = 0; j < 8; j++) {
                uint32_t boff = ((uint32_t)(j * 8) + b_row) * 144 +
                                ((uint32_t)(s * 16) + b_koff) * 2;
                uint32_t bh[2], bl[2];
                ldmx2(bh, sb + BH_OFF + boff);
                ldmx2(bl, sb + BL_OFF + boff);
                mma_bf16(acc[j], ah, bh);
                mma_bf16(acc[j], ah, bl);
                mma_bf16(acc[j], al, bh);
            }
        }
        __syncthreads();
    }

    float* Cs = (float*)(sm + AH_OFF);     // [128][68]
    const int g = lane >> 2, tg = lane & 3;
#pragma unroll
    for (int j = 0; j < 8; j++) {
        Cs[(w * 16 + g) * 68 + j * 8 + tg * 2 + 0] = acc[j][0];
        Cs[(w * 16 + g) * 68 + j * 8 + tg * 2 + 1] = acc[j][1];
        Cs[(w * 16 + g + 8) * 68 + j * 8 + tg * 2 + 0] = acc[j][2];
        Cs[(w * 16 + g + 8) * 68 + j * 8 + tg * 2 + 1] = acc[j][3];
    }
    __syncthreads();

    float* rnp = (float*)(sm + RN_OFF);
    if (MODE == 1) {
        if (tid < 128) {
            float s = 0.f;
#pragma unroll 8
            for (int c = 0; c < 64; c++) { float v = Cs[tid * 68 + c]; s += v * v; }
            rnp[tid] = rsqrtf(s * (1.0f / 64.0f) + 1e-6f);
        }
        __syncthreads();
    }

    for (int e = tid; e < 8192; e += 256) {
        int r = e >> 6, d = e & 63;
        int grow = row0 + r;
        if (MODE == 1) {
            int b = grow >> 11, l = grow & 2047;
            float nrm = rnp[r];
            float v = Cs[r * 68 + d] * nrm * nw[d];
            int dp = d ^ 32;
            float pv = Cs[r * 68 + dp] * nrm * nw[dp];
            float rh = (d < 32) ? -pv : pv;
            float cv = cosp[(size_t)grow * 64 + d];
            float sv = sinp[(size_t)grow * 64 + d];
            outp[(((size_t)(b * HC + head) * LQC + l) << 6) + d] = v * cv + rh * sv;
        } else if (MODE == 0) {
            int b = grow >> 11, l = grow & 2047;
            outp[(((size_t)(b * HC + head) * LQC + l) << 6) + d] = Cs[r * 68 + d];
        } else {
            outp[(size_t)grow * DIMC + head * 64 + d] = Cs[r * 68 + d];
        }
    }
}

// =====================================================================
// Tensor-core flash attention. CTA = 128 q rows of one (b,h), 8 warps,
// warp w owns q-strip [w*16, w*16+16). Split-bf16 3-MMA for QK and PV.
// Softmax entirely on FMA pipe (fexp2), quad shuffles for row reduce.
// smem (bytes): Qh/Ql [128][72]bf16, Kh/Kl [128][72], Vh/Vl [128][72],
//               Ph/Pl [128][136]bf16  -> total 180224 (1 CTA/SM)
// =====================================================================
#define QH_OFF 0
#define QL_OFF 18432
#define KH_OFF 36864
#define KL_OFF 55296
#define VH_OFF 73728
#define VL_OFF 92160
#define PH_OFF 110592
#define PL_OFF 145408
#define FA_SMEM 180224

__global__ void __launch_bounds__(256, 1)
flash_mma(const float* __restrict__ gQ,
          const float* __restrict__ gK,
          const float* __restrict__ gV,
          float* __restrict__ gAO)
{
    extern __shared__ __align__(16) char sm[];
    const uint32_t sb = smem_u32(sm);
    const int tid = threadIdx.x;
    const int w = tid >> 5, lane = tid & 31;
    const int bh = blockIdx.y;
    const int q0 = blockIdx.x * 128;
    const int g = lane >> 2, qd = lane & 3;

    const float* Qb = gQ + (size_t)bh * LQC * HDC;
    const float* Kb = gK + (size_t)bh * LKC * HDC;
    const float* Vb = gV + (size_t)bh * LKC * HDC;

    // ---- load + split Q (pre-scaled by 1/sqrt(64)) ----
    for (int e = tid; e < 2048; e += 256) {
        int r = e >> 4, c4 = e & 15;
        float4 v = *(const float4*)&Qb[(size_t)(q0 + r) * 64 + c4 * 4];
        v.x *= 0.125f; v.y *= 0.125f; v.z *= 0.125f; v.w *= 0.125f;
        uint32_t h0, lo0, h1, lo1;
        split2(v.x, v.y, h0, lo0);
        split2(v.z, v.w, h1, lo1);
        uint32_t off = (uint32_t)(r * 72 + c4 * 4) * 2;
        *(uint2*)(sm + QH_OFF + off) = make_uint2(h0, h1);
        *(uint2*)(sm + QL_OFF + off) = make_uint2(lo0, lo1);
    }
    __syncthreads();

    // ---- Q fragments pinned in registers for all tiles ----
    uint32_t qh[4][4], ql[4][4];
    {
        const uint32_t arow = (uint32_t)(w * 16 + (lane & 15));
        const uint32_t akoff = (uint32_t)((lane >> 4) * 8);
#pragma unroll
        for (int s = 0; s < 4; s++) {
            ldmx4(qh[s], sb + QH_OFF + (arow * 72 + (uint32_t)(s * 16) + akoff) * 2);
            ldmx4(ql[s], sb + QL_OFF + (arow * 72 + (uint32_t)(s * 16) + akoff) * 2);
        }
    }

    float accO[8][4] = {};
    float m0 = -1e30f, m1 = -1e30f, l0 = 0.f, l1 = 0.f;

    const uint32_t brow = (uint32_t)(lane & 7);
    const uint32_t bko = (uint32_t)(((lane >> 3) & 1) * 8);
    const uint32_t prow = (uint32_t)(w * 16 + (lane & 15));
    const uint32_t pko = (uint32_t)((lane >> 4) * 8);
    const uint32_t vrow = (uint32_t)(lane & 15);
    const uint32_t pst0 = (uint32_t)((w * 16 + g) * 272 + qd * 4);

    for (int k0 = 0; k0 < LKC; k0 += 128) {
        // ---- load + split K, V tiles ----
        for (int e = tid; e < 2048; e += 256) {
            int r = e >> 4, c4 = e & 15;
            float4 kv = *(const float4*)&Kb[(size_t)(k0 + r) * 64 + c4 * 4];
            float4 vv = *(const float4*)&Vb[(size_t)(k0 + r) * 64 + c4 * 4];
            uint32_t h0, lo0, h1, lo1;
            uint32_t off = (uint32_t)(r * 72 + c4 * 4) * 2;
            split2(kv.x, kv.y, h0, lo0);
            split2(kv.z, kv.w, h1, lo1);
            *(uint2*)(sm + KH_OFF + off) = make_uint2(h0, h1);
            *(uint2*)(sm + KL_OFF + off) = make_uint2(lo0, lo1);
            split2(vv.x, vv.y, h0, lo0);
            split2(vv.z, vv.w, h1, lo1);
            *(uint2*)(sm + VH_OFF + off) = make_uint2(h0, h1);
            *(uint2*)(sm + VL_OFF + off) = make_uint2(lo0, lo1);
        }
        __syncthreads();

        // ---- S = Q K^T (16 n-tiles x 4 k-steps x 3 split-MMAs) ----
        float accS[16][4];
#pragma unroll
        for (int j = 0; j < 16; j++) {
            accS[j][0] = 0.f; accS[j][1] = 0.f; accS[j][2] = 0.f; accS[j][3] = 0.f;
        }
#pragma unroll
        for (int s = 0; s < 4; s++) {
#pragma unroll
            for (int j = 0; j < 16; j++) {
                uint32_t boff = ((uint32_t)(j * 8) + brow) * 144 +
                                ((uint32_t)(s * 16) + bko) * 2;
                uint32_t kh[2], kl[2];
                ldmx2(kh, sb + KH_OFF + boff);
                ldmx2(kl, sb + KL_OFF + boff);
                mma_bf16(accS[j], qh[s], kh);
                mma_bf16(accS[j], qh[s], kl);
                mma_bf16(accS[j], ql[s], kh);
            }
        }

        // ---- online softmax (rows g and g+8 of warp strip) ----
        float mx0 = -1e30f, mx1 = -1e30f;
#pragma unroll
        for (int j = 0; j < 16; j++) {
            mx0 = fmaxf(mx0, fmaxf(accS[j][0], accS[j][1]));
            mx1 = fmaxf(mx1, fmaxf(accS[j][2], accS[j][3]));
        }
        mx0 = fmaxf(mx0, __shfl_xor_sync(0xffffffffu, mx0, 1));
        mx0 = fmaxf(mx0, __shfl_xor_sync(0xffffffffu, mx0, 2));
        mx1 = fmaxf(mx1, __shfl_xor_sync(0xffffffffu, mx1, 1));
        mx1 = fmaxf(mx1, __shfl_xor_sync(0xffffffffu, mx1, 2));
        float m0n = fmaxf(m0, mx0), m1n = fmaxf(m1, mx1);
        float al0 = fexp2((m0 - m0n) * L2E);
        float al1 = fexp2((m1 - m1n) * L2E);
        float rs0 = 0.f, rs1 = 0.f;
#pragma unroll
        for (int j = 0; j < 16; j++) {
            float p0 = fexp2((accS[j][0] - m0n) * L2E);
            float p1 = fexp2((accS[j][1] - m0n) * L2E);
            float p2 = fexp2((accS[j][2] - m1n) * L2E);
            float p3 = fexp2((accS[j][3] - m1n) * L2E);
            rs0 += p0 + p1;
            rs1 += p2 + p3;
            uint32_t h, lo;
            split2(p0, p1, h, lo);
            *(uint32_t*)(sm + PH_OFF + pst0 + (uint32_t)(j * 16)) = h;
            *(uint32_t*)(sm + PL_OFF + pst0 + (uint32_t)(j * 16)) = lo;
            split2(p2, p3, h, lo);
            *(uint32_t*)(sm + PH_OFF + pst0 + 2176u + (uint32_t)(j * 16)) = h;   // +8 rows
            *(uint32_t*)(sm + PL_OFF + pst0 + 2176u + (uint32_t)(j * 16)) = lo;
        }
        rs0 += __shfl_xor_sync(0xffffffffu, rs0, 1);
        rs0 += __shfl_xor_sync(0xffffffffu, rs0, 2);
        rs1 += __shfl_xor_sync(0xffffffffu, rs1, 1);
        rs1 += __shfl_xor_sync(0xffffffffu, rs1, 2);
        l0 = l0 * al0 + rs0;
        l1 = l1 * al1 + rs1;
        m0 = m0n; m1 = m1n;
#pragma unroll
        for (int j = 0; j < 8; j++) {
            accO[j][0] *= al0; accO[j][1] *= al0;
            accO[j][2] *= al1; accO[j][3] *= al1;
        }
        __syncthreads();   // P visible to all warps

        // ---- O += P V (8 k-steps x 8 n-tiles x 3 split-MMAs) ----
#pragma unroll
        for (int s = 0; s < 8; s++) {
            uint32_t ph[4], pl[4];
            uint32_t poff = prow * 272 + ((uint32_t)(s * 16) + pko) * 2;
            ldmx4(ph, sb + PH_OFF + poff);
            ldmx4(pl, sb + PL_OFF + poff);
            uint32_t vro = ((uint32_t)(s * 16) + vrow) * 144;
#pragma unroll
            for (int j = 0; j < 8; j++) {
                uint32_t vh[2], vl[2];
                ldmx2t(vh, sb + VH_OFF + vro + (uint32_t)(j * 16));
                ldmx2t(vl, sb + VL_OFF + vro + (uint32_t)(j * 16));
                mma_bf16(accO[j], ph, vh);
                mma_bf16(accO[j], ph, vl);
                mma_bf16(accO[j], pl, vh);
            }
        }
        __syncthreads();   // protect K/V/P before next tile's overwrite
    }

    // ---- normalize and write AO ----
    const int b = bh / HC, h = bh % HC;
    const float inv0 = 1.0f / l0, inv1 = 1.0f / l1;
    const size_t base0 = (size_t)(b * LQC + q0 + w * 16 + g) * DIMC + h * 64;
    const size_t base1 = base0 + (size_t)8 * DIMC;
#pragma unroll
    for (int j = 0; j < 8; j++) {
        *(float2*)&gAO[base0 + j * 8 + qd * 2] =
            make_float2(accO[j][0] * inv0, accO[j][1] * inv0);
        *(float2*)&gAO[base1 + j * 8 + qd * 2] =
            make_float2(accO[j][2] * inv1, accO[j][3] * inv1);
    }
}

// =====================================================================
// launch
// =====================================================================
extern "C" void kernel_launch(void* const* d_in, const int* in_sizes, int n_in,
                              void* d_out, int out_size)
{
    const float* queries = (const float*)d_in[0];
    const float* context = (const float*)d_in[1];
    const float* qcos    = (const float*)d_in[2];
    const float* qsin    = (const float*)d_in[3];
    const float* kcos    = (const float*)d_in[4];
    const float* ksin    = (const float*)d_in[5];
    const float* Wq      = (const float*)d_in[6];
    const float* Wkv     = (const float*)d_in[7];
    const float* Wo      = (const float*)d_in[8];
    const float* qnw     = (const float*)d_in[9];
    const float* knw     = (const float*)d_in[10];
    float* out = (float*)d_out;

    float *pQ, *pK, *pV, *pAO;
    cudaGetSymbolAddress((void**)&pQ,  g_Q);
    cudaGetSymbolAddress((void**)&pK,  g_K);
    cudaGetSymbolAddress((void**)&pV,  g_V);
    cudaGetSymbolAddress((void**)&pAO, g_AO);

    cudaFuncSetAttribute(mma_gemm<0>, cudaFuncAttributeMaxDynamicSharedMemorySize, SMEM_MM);
    cudaFuncSetAttribute(mma_gemm<1>, cudaFuncAttributeMaxDynamicSharedMemorySize, SMEM_MM);
    cudaFuncSetAttribute(mma_gemm<2>, cudaFuncAttributeMaxDynamicSharedMemorySize, SMEM_MM);
    cudaFuncSetAttribute(flash_mma, cudaFuncAttributeMaxDynamicSharedMemorySize, FA_SMEM);

    dim3 blk(256);
    dim3 gg(NR / 128, HC);

    mma_gemm<1><<<gg, blk, SMEM_MM>>>(queries, Wq,  0,    qcos, qsin, qnw, pQ);
    mma_gemm<1><<<gg, blk, SMEM_MM>>>(context, Wkv, 0,    kcos, ksin, knw, pK);
    mma_gemm<0><<<gg, blk, SMEM_MM>>>(context, Wkv, DIMC,
                                      (const float*)0, (const float*)0,
                                      (const float*)0, pV);

    flash_mma<<<dim3(LQC / 128, BC * HC), blk, FA_SMEM>>>(pQ, pK, pV, pAO);

    mma_gemm<2><<<gg, blk, SMEM_MM>>>(pAO, Wo, 0,
                                      (const float*)0, (const float*)0,
                                      (const float*)0, out);
}

// round 10
// speedup vs baseline: 2.8461x; 1.0160x over previous
#include <cuda_runtime.h>
#include <cuda_bf16.h>
#include <cstdint>
#include <cstddef>

#define DIMC 768
#define HC 12
#define HDC 64
#define BC 4
#define LQC 2048
#define LKC 2048
#define NR (BC * LQC)   // 8192 rows

// ---------------- scratch (no allocations allowed) ----------------
__device__ float g_Q[BC * HC * LQC * HDC];   // (b,h,l,d) fp32
__device__ float g_K[BC * HC * LKC * HDC];
__device__ float g_V[BC * HC * LKC * HDC];
__device__ float g_AO[BC * LQC * DIMC];      // (b,l,dim) fp32

// =====================================================================
// mma.sync helpers (compute_100-safe legacy tensor-core path)
// =====================================================================
__device__ __forceinline__ uint32_t smem_u32(const void* p) {
    uint32_t a;
    asm("{ .reg .u64 t; cvta.to.shared.u64 t, %1; cvt.u32.u64 %0, t; }"
        : "=r"(a) : "l"(p));
    return a;
}
__device__ __forceinline__ void ldmx4(uint32_t* r, uint32_t a) {
    asm volatile("ldmatrix.sync.aligned.m8n8.x4.shared.b16 {%0,%1,%2,%3}, [%4];"
                 : "=r"(r[0]), "=r"(r[1]), "=r"(r[2]), "=r"(r[3]) : "r"(a));
}
__device__ __forceinline__ void ldmx2(uint32_t* r, uint32_t a) {
    asm volatile("ldmatrix.sync.aligned.m8n8.x2.shared.b16 {%0,%1}, [%2];"
                 : "=r"(r[0]), "=r"(r[1]) : "r"(a));
}
__device__ __forceinline__ void ldmx2t(uint32_t* r, uint32_t a) {
    asm volatile("ldmatrix.sync.aligned.m8n8.x2.trans.shared.b16 {%0,%1}, [%2];"
                 : "=r"(r[0]), "=r"(r[1]) : "r"(a));
}
__device__ __forceinline__ void mma_bf16(float* c, const uint32_t* a,
                                         const uint32_t* b) {
    asm volatile(
        "mma.sync.aligned.m16n8k16.row.col.f32.bf16.bf16.f32 "
        "{%0,%1,%2,%3}, {%4,%5,%6,%7}, {%8,%9}, {%0,%1,%2,%3};"
        : "+f"(c[0]), "+f"(c[1]), "+f"(c[2]), "+f"(c[3])
        : "r"(a[0]), "r"(a[1]), "r"(a[2]), "r"(a[3]), "r"(b[0]), "r"(b[1]));
}
// float -> (hi, lo) bf16 split, packed pairwise
__device__ __forceinline__ void split2(float x, float y, uint32_t& h, uint32_t& l) {
    __nv_bfloat16 hx = __float2bfloat16(x);
    __nv_bfloat16 hy = __float2bfloat16(y);
    __nv_bfloat16 lx = __float2bfloat16(x - __bfloat162float(hx));
    __nv_bfloat16 ly = __float2bfloat16(y - __bfloat162float(hy));
    h = (uint32_t)__bfloat16_as_ushort(hx) | ((uint32_t)__bfloat16_as_ushort(hy) << 16);
    l = (uint32_t)__bfloat16_as_ushort(lx) | ((uint32_t)__bfloat16_as_ushort(ly) << 16);
}
// FMA-pipe exp2 (no MUFU): magic-number round + deg-5 Taylor + exponent splice.
__device__ __forceinline__ float fexp2(float t) {
    t = fmaxf(t, -126.0f);
    float r = t + 12582912.0f;             // 1.5 * 2^23
    int32_t ib = __float_as_int(r);
    float nf = r - 12582912.0f;
    float f = t - nf;                      // f in [-0.5, 0.5]
    float p = 0.00133336f;
    p = fmaf(p, f, 0.00961813f);
    p = fmaf(p, f, 0.05550411f);
    p = fmaf(p, f, 0.24022651f);
    p = fmaf(p, f, 0.69314718f);
    p = fmaf(p, f, 1.0f);
    return __int_as_float(__float_as_int(p) + (ib << 23));
}
#define L2E 1.4426950408889634f

// =====================================================================
// mma.sync split-bf16 GEMM (math unchanged from R8/R9 — verified 9e-6):
// now __launch_bounds__(256,2) so two CTAs co-reside per SM.
// =====================================================================
#define AH_OFF 0
#define AL_OFF 18432
#define BH_OFF 36864
#define BL_OFF 46080
#define RN_OFF 55296
#define SMEM_MM (55296 + 512)

template <int MODE>
__global__ void __launch_bounds__(256, 2)
mma_gemm(const float* __restrict__ Ag, const float* __restrict__ Wg,
         int w_off,
         const float* __restrict__ cosp, const float* __restrict__ sinp,
         const float* __restrict__ nw, float* __restrict__ outp)
{
    extern __shared__ __align__(16) char sm[];
    const int tid = threadIdx.x;
    const int w = tid >> 5, lane = tid & 31;
    const int row0 = blockIdx.x * 128;
    const int head = blockIdx.y;
    const int c0 = w_off + head * 64;

    float acc[8][4] = {};

    const uint32_t sb = smem_u32(sm);
    const uint32_t a_row = (uint32_t)(w * 16 + (lane & 15));
    const uint32_t a_koff = (uint32_t)((lane >> 4) * 8);
    const uint32_t ah_base = sb + AH_OFF + (a_row * 72 + a_koff) * 2;
    const uint32_t al_base = sb + AL_OFF + (a_row * 72 + a_koff) * 2;
    const uint32_t b_row = (uint32_t)(lane & 7);
    const uint32_t b_koff = (uint32_t)(((lane >> 3) & 1) * 8);

    for (int kc = 0; kc < 12; kc++) {
        for (int e = tid; e < 2048; e += 256) {
            int r = e >> 4, c4 = e & 15;
            float4 v = *(const float4*)&Ag[(size_t)(row0 + r) * DIMC + kc * 64 + c4 * 4];
            uint32_t h0, l0, h1, l1;
            split2(v.x, v.y, h0, l0);
            split2(v.z, v.w, h1, l1);
            uint32_t off = (uint32_t)(r * 72 + c4 * 4) * 2;
            *(uint2*)(sm + AH_OFF + off) = make_uint2(h0, h1);
            *(uint2*)(sm + AL_OFF + off) = make_uint2(l0, l1);
        }
        for (int e = tid; e < 1024; e += 256) {
            int r = e >> 4, c4 = e & 15;
            float4 v = *(const float4*)&Wg[(size_t)(c0 + r) * DIMC + kc * 64 + c4 * 4];
            uint32_t h0, l0, h1, l1;
            split2(v.x, v.y, h0, l0);
            split2(v.z, v.w, h1, l1);
            uint32_t off = (uint32_t)(r * 72 + c4 * 4) * 2;
            *(uint2*)(sm + BH_OFF + off) = make_uint2(h0, h1);
            *(uint2*)(sm + BL_OFF + off) = make_uint2(l0, l1);
        }
        __syncthreads();

#pragma unroll
        for (int s = 0; s < 4; s++) {
            uint32_t ah[4], al[4];
            ldmx4(ah, ah_base + (uint32_t)(s * 16) * 2);
            ldmx4(al, al_base + (uint32_t)(s * 16) * 2);
#pragma unroll
            for (int j = 0; j < 8; j++) {
                uint32_t boff = ((uint32_t)(j * 8) + b_row) * 144 +
                                ((uint32_t)(s * 16) + b_koff) * 2;
                uint32_t bh[2], bl[2];
                ldmx2(bh, sb + BH_OFF + boff);
                ldmx2(bl, sb + BL_OFF + boff);
                mma_bf16(acc[j], ah, bh);
                mma_bf16(acc[j], ah, bl);
                mma_bf16(acc[j], al, bh);
            }
        }
        __syncthreads();
    }

    float* Cs = (float*)(sm + AH_OFF);     // [128][68]
    const int g = lane >> 2, tg = lane & 3;
#pragma unroll
    for (int j = 0; j < 8; j++) {
        Cs[(w * 16 + g) * 68 + j * 8 + tg * 2 + 0] = acc[j][0];
        Cs[(w * 16 + g) * 68 + j * 8 + tg * 2 + 1] = acc[j][1];
        Cs[(w * 16 + g + 8) * 68 + j * 8 + tg * 2 + 0] = acc[j][2];
        Cs[(w * 16 + g + 8) * 68 + j * 8 + tg * 2 + 1] = acc[j][3];
    }
    __syncthreads();

    float* rnp = (float*)(sm + RN_OFF);
    if (MODE == 1) {
        if (tid < 128) {
            float s = 0.f;
#pragma unroll 8
            for (int c = 0; c < 64; c++) { float v = Cs[tid * 68 + c]; s += v * v; }
            rnp[tid] = rsqrtf(s * (1.0f / 64.0f) + 1e-6f);
        }
        __syncthreads();
    }

    for (int e = tid; e < 8192; e += 256) {
        int r = e >> 6, d = e & 63;
        int grow = row0 + r;
        if (MODE == 1) {
            int b = grow >> 11, l = grow & 2047;
            float nrm = rnp[r];
            float v = Cs[r * 68 + d] * nrm * nw[d];
            int dp = d ^ 32;
            float pv = Cs[r * 68 + dp] * nrm * nw[dp];
            float rh = (d < 32) ? -pv : pv;
            float cv = cosp[(size_t)grow * 64 + d];
            float sv = sinp[(size_t)grow * 64 + d];
            outp[(((size_t)(b * HC + head) * LQC + l) << 6) + d] = v * cv + rh * sv;
        } else if (MODE == 0) {
            int b = grow >> 11, l = grow & 2047;
            outp[(((size_t)(b * HC + head) * LQC + l) << 6) + d] = Cs[r * 68 + d];
        } else {
            outp[(size_t)grow * DIMC + head * 64 + d] = Cs[r * 68 + d];
        }
    }
}

// =====================================================================
// Tensor-core flash attention, v2: 128 q x 64 kv tiles, 2 CTAs/SM.
// Q fragments reloaded from smem each tile (saves 32 regs); split-bf16
// 3-MMA for QK and PV; FMA-pipe softmax.
// smem: Qh/Ql [128][72]bf16, Kh/Kl [64][72], Vh/Vl [64][72],
//       Ph/Pl [128][72]  -> 110592 B total -> 2 CTAs/SM.
// =====================================================================
#define QH_OFF 0
#define QL_OFF 18432
#define KH_OFF 36864
#define KL_OFF 46080
#define VH_OFF 55296
#define VL_OFF 64512
#define PH_OFF 73728
#define PL_OFF 92160
#define FA_SMEM 110592

__global__ void __launch_bounds__(256, 2)
flash_mma(const float* __restrict__ gQ,
          const float* __restrict__ gK,
          const float* __restrict__ gV,
          float* __restrict__ gAO)
{
    extern __shared__ __align__(16) char sm[];
    const uint32_t sb = smem_u32(sm);
    const int tid = threadIdx.x;
    const int w = tid >> 5, lane = tid & 31;
    const int bh = blockIdx.y;
    const int q0 = blockIdx.x * 128;
    const int g = lane >> 2, qd = lane & 3;

    const float* Qb = gQ + (size_t)bh * LQC * HDC;
    const float* Kb = gK + (size_t)bh * LKC * HDC;
    const float* Vb = gV + (size_t)bh * LKC * HDC;

    // ---- load + split Q (pre-scaled by 1/sqrt(64)) ----
    for (int e = tid; e < 2048; e += 256) {
        int r = e >> 4, c4 = e & 15;
        float4 v = *(const float4*)&Qb[(size_t)(q0 + r) * 64 + c4 * 4];
        v.x *= 0.125f; v.y *= 0.125f; v.z *= 0.125f; v.w *= 0.125f;
        uint32_t h0, lo0, h1, lo1;
        split2(v.x, v.y, h0, lo0);
        split2(v.z, v.w, h1, lo1);
        uint32_t off = (uint32_t)(r * 72 + c4 * 4) * 2;
        *(uint2*)(sm + QH_OFF + off) = make_uint2(h0, h1);
        *(uint2*)(sm + QL_OFF + off) = make_uint2(lo0, lo1);
    }
    __syncthreads();

    float accO[8][4] = {};
    float m0 = -1e30f, m1 = -1e30f, l0 = 0.f, l1 = 0.f;

    const uint32_t arow = (uint32_t)(w * 16 + (lane & 15));
    const uint32_t akoff = (uint32_t)((lane >> 4) * 8);
    const uint32_t brow = (uint32_t)(lane & 7);
    const uint32_t bko = (uint32_t)(((lane >> 3) & 1) * 8);
    const uint32_t prow = (uint32_t)(w * 16 + (lane & 15));
    const uint32_t pko = (uint32_t)((lane >> 4) * 8);
    const uint32_t vrow = (uint32_t)(lane & 15);
    const uint32_t pst0 = (uint32_t)((w * 16 + g) * 144 + qd * 4);

    for (int k0 = 0; k0 < LKC; k0 += 64) {
        // ---- load + split K, V tiles (64 rows) ----
        for (int e = tid; e < 1024; e += 256) {
            int r = e >> 4, c4 = e & 15;
            float4 kv = *(const float4*)&Kb[(size_t)(k0 + r) * 64 + c4 * 4];
            float4 vv = *(const float4*)&Vb[(size_t)(k0 + r) * 64 + c4 * 4];
            uint32_t h0, lo0, h1, lo1;
            uint32_t off = (uint32_t)(r * 72 + c4 * 4) * 2;
            split2(kv.x, kv.y, h0, lo0);
            split2(kv.z, kv.w, h1, lo1);
            *(uint2*)(sm + KH_OFF + off) = make_uint2(h0, h1);
            *(uint2*)(sm + KL_OFF + off) = make_uint2(lo0, lo1);
            split2(vv.x, vv.y, h0, lo0);
            split2(vv.z, vv.w, h1, lo1);
            *(uint2*)(sm + VH_OFF + off) = make_uint2(h0, h1);
            *(uint2*)(sm + VL_OFF + off) = make_uint2(lo0, lo1);
        }
        __syncthreads();

        // ---- S = Q K^T (8 n-tiles x 4 k-steps x 3 split-MMAs) ----
        float accS[8][4];
#pragma unroll
        for (int j = 0; j < 8; j++) {
            accS[j][0] = 0.f; accS[j][1] = 0.f; accS[j][2] = 0.f; accS[j][3] = 0.f;
        }
#pragma unroll
        for (int s = 0; s < 4; s++) {
            uint32_t qh[4], ql[4];
            uint32_t qoff = (arow * 72 + (uint32_t)(s * 16) + akoff) * 2;
            ldmx4(qh, sb + QH_OFF + qoff);
            ldmx4(ql, sb + QL_OFF + qoff);
#pragma unroll
            for (int j = 0; j < 8; j++) {
                uint32_t boff = ((uint32_t)(j * 8) + brow) * 144 +
                                ((uint32_t)(s * 16) + bko) * 2;
                uint32_t kh[2], kl[2];
                ldmx2(kh, sb + KH_OFF + boff);
                ldmx2(kl, sb + KL_OFF + boff);
                mma_bf16(accS[j], qh, kh);
                mma_bf16(accS[j], qh, kl);
                mma_bf16(accS[j], ql, kh);
            }
        }

        // ---- online softmax (rows g and g+8 of warp strip) ----
        float mx0 = -1e30f, mx1 = -1e30f;
#pragma unroll
        for (int j = 0; j < 8; j++) {
            mx0 = fmaxf(mx0, fmaxf(accS[j][0], accS[j][1]));
            mx1 = fmaxf(mx1, fmaxf(accS[j][2], accS[j][3]));
        }
        mx0 = fmaxf(mx0, __shfl_xor_sync(0xffffffffu, mx0, 1));
        mx0 = fmaxf(mx0, __shfl_xor_sync(0xffffffffu, mx0, 2));
        mx1 = fmaxf(mx1, __shfl_xor_sync(0xffffffffu, mx1, 1));
        mx1 = fmaxf(mx1, __shfl_xor_sync(0xffffffffu, mx1, 2));
        float m0n = fmaxf(m0, mx0), m1n = fmaxf(m1, mx1);
        float al0 = fexp2((m0 - m0n) * L2E);
        float al1 = fexp2((m1 - m1n) * L2E);
        float rs0 = 0.f, rs1 = 0.f;
#pragma unroll
        for (int j = 0; j < 8; j++) {
            float p0 = fexp2((accS[j][0] - m0n) * L2E);
            float p1 = fexp2((accS[j][1] - m0n) * L2E);
            float p2 = fexp2((accS[j][2] - m1n) * L2E);
            float p3 = fexp2((accS[j][3] - m1n) * L2E);
            rs0 += p0 + p1;
            rs1 += p2 + p3;
            uint32_t h, lo;
            split2(p0, p1, h, lo);
            *(uint32_t*)(sm + PH_OFF + pst0 + (uint32_t)(j * 16)) = h;
            *(uint32_t*)(sm + PL_OFF + pst0 + (uint32_t)(j * 16)) = lo;
            split2(p2, p3, h, lo);
            *(uint32_t*)(sm + PH_OFF + pst0 + 1152u + (uint32_t)(j * 16)) = h;   // +8 rows
            *(uint32_t*)(sm + PL_OFF + pst0 + 1152u + (uint32_t)(j * 16)) = lo;
        }
        rs0 += __shfl_xor_sync(0xffffffffu, rs0, 1);
        rs0 += __shfl_xor_sync(0xffffffffu, rs0, 2);
        rs1 += __shfl_xor_sync(0xffffffffu, rs1, 1);
        rs1 += __shfl_xor_sync(0xffffffffu, rs1, 2);
        l0 = l0 * al0 + rs0;
        l1 = l1 * al1 + rs1;
        m0 = m0n; m1 = m1n;
#pragma unroll
        for (int j = 0; j < 8; j++) {
            accO[j][0] *= al0; accO[j][1] *= al0;
            accO[j][2] *= al1; accO[j][3] *= al1;
        }
        __syncthreads();   // P visible to all warps

        // ---- O += P V (4 k-steps x 8 n-tiles x 3 split-MMAs) ----
#pragma unroll
        for (int s = 0; s < 4; s++) {
            uint32_t ph[4], pl[4];
            uint32_t poff = prow * 144 + ((uint32_t)(s * 16) + pko) * 2;
            ldmx4(ph, sb + PH_OFF + poff);
            ldmx4(pl, sb + PL_OFF + poff);
            uint32_t vro = ((uint32_t)(s * 16) + vrow) * 144;
#pragma unroll
            for (int j = 0; j < 8; j++) {
                uint32_t vh[2], vl[2];
                ldmx2t(vh, sb + VH_OFF + vro + (uint32_t)(j * 16));
                ldmx2t(vl, sb + VL_OFF + vro + (uint32_t)(j * 16));
                mma_bf16(accO[j], ph, vh);
                mma_bf16(accO[j], ph, vl);
                mma_bf16(accO[j], pl, vh);
            }
        }
        __syncthreads();   // protect K/V/P before next tile's overwrite
    }

    // ---- normalize and write AO ----
    const int b = bh / HC, h = bh % HC;
    const float inv0 = 1.0f / l0, inv1 = 1.0f / l1;
    const size_t base0 = (size_t)(b * LQC + q0 + w * 16 + g) * DIMC + h * 64;
    const size_t base1 = base0 + (size_t)8 * DIMC;
#pragma unroll
    for (int j = 0; j < 8; j++) {
        *(float2*)&gAO[base0 + j * 8 + qd * 2] =
            make_float2(accO[j][0] * inv0, accO[j][1] * inv0);
        *(float2*)&gAO[base1 + j * 8 + qd * 2] =
            make_float2(accO[j][2] * inv1, accO[j][3] * inv1);
    }
}

// =====================================================================
// launch
// =====================================================================
extern "C" void kernel_launch(void* const* d_in, const int* in_sizes, int n_in,
                              void* d_out, int out_size)
{
    const float* queries = (const float*)d_in[0];
    const float* context = (const float*)d_in[1];
    const float* qcos    = (const float*)d_in[2];
    const float* qsin    = (const float*)d_in[3];
    const float* kcos    = (const float*)d_in[4];
    const float* ksin    = (const float*)d_in[5];
    const float* Wq      = (const float*)d_in[6];
    const float* Wkv     = (const float*)d_in[7];
    const float* Wo      = (const float*)d_in[8];
    const float* qnw     = (const float*)d_in[9];
    const float* knw     = (const float*)d_in[10];
    float* out = (float*)d_out;

    float *pQ, *pK, *pV, *pAO;
    cudaGetSymbolAddress((void**)&pQ,  g_Q);
    cudaGetSymbolAddress((void**)&pK,  g_K);
    cudaGetSymbolAddress((void**)&pV,  g_V);
    cudaGetSymbolAddress((void**)&pAO, g_AO);

    cudaFuncSetAttribute(mma_gemm<0>, cudaFuncAttributeMaxDynamicSharedMemorySize, SMEM_MM);
    cudaFuncSetAttribute(mma_gemm<1>, cudaFuncAttributeMaxDynamicSharedMemorySize, SMEM_MM);
    cudaFuncSetAttribute(mma_gemm<2>, cudaFuncAttributeMaxDynamicSharedMemorySize, SMEM_MM);
    cudaFuncSetAttribute(flash_mma, cudaFuncAttributeMaxDynamicSharedMemorySize, FA_SMEM);

    dim3 blk(256);
    dim3 gg(NR / 128, HC);

    mma_gemm<1><<<gg, blk, SMEM_MM>>>(queries, Wq,  0,    qcos, qsin, qnw, pQ);
    mma_gemm<1><<<gg, blk, SMEM_MM>>>(context, Wkv, 0,    kcos, ksin, knw, pK);
    mma_gemm<0><<<gg, blk, SMEM_MM>>>(context, Wkv, DIMC,
                                      (const float*)0, (const float*)0,
                                      (const float*)0, pV);

    flash_mma<<<dim3(LQC / 128, BC * HC), blk, FA_SMEM>>>(pQ, pK, pV, pAO);

    mma_gemm<2><<<gg, blk, SMEM_MM>>>(pAO, Wo, 0,
                                      (const float*)0, (const float*)0,
                                      (const float*)0, out);
}

// round 11
// speedup vs baseline: 3.3120x; 1.1637x over previous
#include <cuda_runtime.h>
#include <cuda_bf16.h>
#include <cstdint>
#include <cstddef>

#define DIMC 768
#define HC 12
#define HDC 64
#define BC 4
#define LQC 2048
#define LKC 2048
#define NR (BC * LQC)   // 8192 rows

// ---------------- scratch (no allocations allowed) ----------------
__device__ float g_Q[BC * HC * LQC * HDC];   // (b,h,l,d) fp32
__device__ float g_K[BC * HC * LKC * HDC];
__device__ float g_V[BC * HC * LKC * HDC];
__device__ float g_AO[BC * LQC * DIMC];      // (b,l,dim) fp32

// =====================================================================
// mma.sync helpers (compute_100-safe legacy tensor-core path)
// =====================================================================
__device__ __forceinline__ uint32_t smem_u32(const void* p) {
    uint32_t a;
    asm("{ .reg .u64 t; cvta.to.shared.u64 t, %1; cvt.u32.u64 %0, t; }"
        : "=r"(a) : "l"(p));
    return a;
}
__device__ __forceinline__ void ldmx4(uint32_t* r, uint32_t a) {
    asm volatile("ldmatrix.sync.aligned.m8n8.x4.shared.b16 {%0,%1,%2,%3}, [%4];"
                 : "=r"(r[0]), "=r"(r[1]), "=r"(r[2]), "=r"(r[3]) : "r"(a));
}
__device__ __forceinline__ void ldmx4t(uint32_t* r, uint32_t a) {
    asm volatile("ldmatrix.sync.aligned.m8n8.x4.trans.shared.b16 {%0,%1,%2,%3}, [%4];"
                 : "=r"(r[0]), "=r"(r[1]), "=r"(r[2]), "=r"(r[3]) : "r"(a));
}
__device__ __forceinline__ void ldmx2(uint32_t* r, uint32_t a) {
    asm volatile("ldmatrix.sync.aligned.m8n8.x2.shared.b16 {%0,%1}, [%2];"
                 : "=r"(r[0]), "=r"(r[1]) : "r"(a));
}
__device__ __forceinline__ void mma_bf16(float* c, const uint32_t* a,
                                         const uint32_t* b) {
    asm volatile(
        "mma.sync.aligned.m16n8k16.row.col.f32.bf16.bf16.f32 "
        "{%0,%1,%2,%3}, {%4,%5,%6,%7}, {%8,%9}, {%0,%1,%2,%3};"
        : "+f"(c[0]), "+f"(c[1]), "+f"(c[2]), "+f"(c[3])
        : "r"(a[0]), "r"(a[1]), "r"(a[2]), "r"(a[3]), "r"(b[0]), "r"(b[1]));
}
// float -> (hi, lo) bf16 split, packed pairwise
__device__ __forceinline__ void split2(float x, float y, uint32_t& h, uint32_t& l) {
    __nv_bfloat16 hx = __float2bfloat16(x);
    __nv_bfloat16 hy = __float2bfloat16(y);
    __nv_bfloat16 lx = __float2bfloat16(x - __bfloat162float(hx));
    __nv_bfloat16 ly = __float2bfloat16(y - __bfloat162float(hy));
    h = (uint32_t)__bfloat16_as_ushort(hx) | ((uint32_t)__bfloat16_as_ushort(hy) << 16);
    l = (uint32_t)__bfloat16_as_ushort(lx) | ((uint32_t)__bfloat16_as_ushort(ly) << 16);
}
// FMA-pipe exp2 (no MUFU): magic-number round + deg-5 Taylor + exponent splice.
__device__ __forceinline__ float fexp2(float t) {
    t = fmaxf(t, -126.0f);
    float r = t + 12582912.0f;             // 1.5 * 2^23
    int32_t ib = __float_as_int(r);
    float nf = r - 12582912.0f;
    float f = t - nf;                      // f in [-0.5, 0.5]
    float p = 0.00133336f;
    p = fmaf(p, f, 0.00961813f);
    p = fmaf(p, f, 0.05550411f);
    p = fmaf(p, f, 0.24022651f);
    p = fmaf(p, f, 0.69314718f);
    p = fmaf(p, f, 1.0f);
    return __int_as_float(__float_as_int(p) + (ib << 23));
}
#define L2E 1.4426950408889634f

// =====================================================================
// mma.sync split-bf16 GEMM — exact R9 configuration (577 us measured):
// plain __launch_bounds__(256), no reg cap.
// =====================================================================
#define AH_OFF 0
#define AL_OFF 18432
#define BH_OFF 36864
#define BL_OFF 46080
#define RN_OFF 55296
#define SMEM_MM (55296 + 512)

template <int MODE>
__global__ void __launch_bounds__(256)
mma_gemm(const float* __restrict__ Ag, const float* __restrict__ Wg,
         int w_off,
         const float* __restrict__ cosp, const float* __restrict__ sinp,
         const float* __restrict__ nw, float* __restrict__ outp)
{
    extern __shared__ __align__(16) char sm[];
    const int tid = threadIdx.x;
    const int w = tid >> 5, lane = tid & 31;
    const int row0 = blockIdx.x * 128;
    const int head = blockIdx.y;
    const int c0 = w_off + head * 64;

    float acc[8][4] = {};

    const uint32_t sb = smem_u32(sm);
    const uint32_t a_row = (uint32_t)(w * 16 + (lane & 15));
    const uint32_t a_koff = (uint32_t)((lane >> 4) * 8);
    const uint32_t ah_base = sb + AH_OFF + (a_row * 72 + a_koff) * 2;
    const uint32_t al_base = sb + AL_OFF + (a_row * 72 + a_koff) * 2;
    const uint32_t b_row = (uint32_t)(lane & 7);
    const uint32_t b_koff = (uint32_t)(((lane >> 3) & 1) * 8);

    for (int kc = 0; kc < 12; kc++) {
        for (int e = tid; e < 2048; e += 256) {
            int r = e >> 4, c4 = e & 15;
            float4 v = *(const float4*)&Ag[(size_t)(row0 + r) * DIMC + kc * 64 + c4 * 4];
            uint32_t h0, l0, h1, l1;
            split2(v.x, v.y, h0, l0);
            split2(v.z, v.w, h1, l1);
            uint32_t off = (uint32_t)(r * 72 + c4 * 4) * 2;
            *(uint2*)(sm + AH_OFF + off) = make_uint2(h0, h1);
            *(uint2*)(sm + AL_OFF + off) = make_uint2(l0, l1);
        }
        for (int e = tid; e < 1024; e += 256) {
            int r = e >> 4, c4 = e & 15;
            float4 v = *(const float4*)&Wg[(size_t)(c0 + r) * DIMC + kc * 64 + c4 * 4];
            uint32_t h0, l0, h1, l1;
            split2(v.x, v.y, h0, l0);
            split2(v.z, v.w, h1, l1);
            uint32_t off = (uint32_t)(r * 72 + c4 * 4) * 2;
            *(uint2*)(sm + BH_OFF + off) = make_uint2(h0, h1);
            *(uint2*)(sm + BL_OFF + off) = make_uint2(l0, l1);
        }
        __syncthreads();

#pragma unroll
        for (int s = 0; s < 4; s++) {
            uint32_t ah[4], al[4];
            ldmx4(ah, ah_base + (uint32_t)(s * 16) * 2);
            ldmx4(al, al_base + (uint32_t)(s * 16) * 2);
#pragma unroll
            for (int j = 0; j < 8; j++) {
                uint32_t boff = ((uint32_t)(j * 8) + b_row) * 144 +
                                ((uint32_t)(s * 16) + b_koff) * 2;
                uint32_t bh[2], bl[2];
                ldmx2(bh, sb + BH_OFF + boff);
                ldmx2(bl, sb + BL_OFF + boff);
                mma_bf16(acc[j], ah, bh);
                mma_bf16(acc[j], ah, bl);
                mma_bf16(acc[j], al, bh);
            }
        }
        __syncthreads();
    }

    float* Cs = (float*)(sm + AH_OFF);     // [128][68]
    const int g = lane >> 2, tg = lane & 3;
#pragma unroll
    for (int j = 0; j < 8; j++) {
        Cs[(w * 16 + g) * 68 + j * 8 + tg * 2 + 0] = acc[j][0];
        Cs[(w * 16 + g) * 68 + j * 8 + tg * 2 + 1] = acc[j][1];
        Cs[(w * 16 + g + 8) * 68 + j * 8 + tg * 2 + 0] = acc[j][2];
        Cs[(w * 16 + g + 8) * 68 + j * 8 + tg * 2 + 1] = acc[j][3];
    }
    __syncthreads();

    float* rnp = (float*)(sm + RN_OFF);
    if (MODE == 1) {
        if (tid < 128) {
            float s = 0.f;
#pragma unroll 8
            for (int c = 0; c < 64; c++) { float v = Cs[tid * 68 + c]; s += v * v; }
            rnp[tid] = rsqrtf(s * (1.0f / 64.0f) + 1e-6f);
        }
        __syncthreads();
    }

    for (int e = tid; e < 8192; e += 256) {
        int r = e >> 6, d = e & 63;
        int grow = row0 + r;
        if (MODE == 1) {
            int b = grow >> 11, l = grow & 2047;
            float nrm = rnp[r];
            float v = Cs[r * 68 + d] * nrm * nw[d];
            int dp = d ^ 32;
            float pv = Cs[r * 68 + dp] * nrm * nw[dp];
            float rh = (d < 32) ? -pv : pv;
            float cv = cosp[(size_t)grow * 64 + d];
            float sv = sinp[(size_t)grow * 64 + d];
            outp[(((size_t)(b * HC + head) * LQC + l) << 6) + d] = v * cv + rh * sv;
        } else if (MODE == 0) {
            int b = grow >> 11, l = grow & 2047;
            outp[(((size_t)(b * HC + head) * LQC + l) << 6) + d] = Cs[r * 68 + d];
        } else {
            outp[(size_t)grow * DIMC + head * 64 + d] = Cs[r * 68 + d];
        }
    }
}

// =====================================================================
// Tensor-core flash attention v3: 128 q x 128 kv K/V tiles, 2 inner
// 64-col softmax iterations, P entirely in registers (C-frag == A-frag
// identity), x4 ldmatrix for K and V fragments. 2 CTAs/SM.
// smem: Qh/Ql [128][72]bf16, Kh/Kl [128][72], Vh/Vl [128][72] = 110592 B
// =====================================================================
#define QH_OFF 0
#define QL_OFF 18432
#define KH_OFF 36864
#define KL_OFF 55296
#define VH_OFF 73728
#define VL_OFF 92160
#define FA_SMEM 110592

__global__ void __launch_bounds__(256, 2)
flash_mma(const float* __restrict__ gQ,
          const float* __restrict__ gK,
          const float* __restrict__ gV,
          float* __restrict__ gAO)
{
    extern __shared__ __align__(16) char sm[];
    const uint32_t sb = smem_u32(sm);
    const int tid = threadIdx.x;
    const int w = tid >> 5, lane = tid & 31;
    const int bh = blockIdx.y;
    const int q0 = blockIdx.x * 128;
    const int g = lane >> 2, qd = lane & 3;

    const float* Qb = gQ + (size_t)bh * LQC * HDC;
    const float* Kb = gK + (size_t)bh * LKC * HDC;
    const float* Vb = gV + (size_t)bh * LKC * HDC;

    // ---- load + split Q (pre-scaled by 1/sqrt(64)) ----
    for (int e = tid; e < 2048; e += 256) {
        int r = e >> 4, c4 = e & 15;
        float4 v = *(const float4*)&Qb[(size_t)(q0 + r) * 64 + c4 * 4];
        v.x *= 0.125f; v.y *= 0.125f; v.z *= 0.125f; v.w *= 0.125f;
        uint32_t h0, lo0, h1, lo1;
        split2(v.x, v.y, h0, lo0);
        split2(v.z, v.w, h1, lo1);
        uint32_t off = (uint32_t)(r * 72 + c4 * 4) * 2;
        *(uint2*)(sm + QH_OFF + off) = make_uint2(h0, h1);
        *(uint2*)(sm + QL_OFF + off) = make_uint2(lo0, lo1);
    }
    __syncthreads();

    float accO[8][4] = {};
    float m0 = -1e30f, m1 = -1e30f, l0 = 0.f, l1 = 0.f;

    const uint32_t arow = (uint32_t)(w * 16 + (lane & 15));
    const uint32_t akoff = (uint32_t)((lane >> 4) * 8);
    // K x4 B-frag addressing: 2 n-tiles per load
    const uint32_t k_r = (uint32_t)(((lane >> 4) & 1) * 8 + (lane & 7));
    const uint32_t k_c = (uint32_t)(((lane >> 3) & 1) * 8);
    // V x4t B-frag addressing: rows = kv idx, 2 d-tiles per load
    const uint32_t v_r = (uint32_t)(lane & 15);
    const uint32_t v_c = (uint32_t)(((lane >> 4) & 1) * 16);

    for (int k0 = 0; k0 < LKC; k0 += 128) {
        // ---- load + split K, V tiles (128 rows) ----
        for (int e = tid; e < 2048; e += 256) {
            int r = e >> 4, c4 = e & 15;
            float4 kv = *(const float4*)&Kb[(size_t)(k0 + r) * 64 + c4 * 4];
            float4 vv = *(const float4*)&Vb[(size_t)(k0 + r) * 64 + c4 * 4];
            uint32_t h0, lo0, h1, lo1;
            uint32_t off = (uint32_t)(r * 72 + c4 * 4) * 2;
            split2(kv.x, kv.y, h0, lo0);
            split2(kv.z, kv.w, h1, lo1);
            *(uint2*)(sm + KH_OFF + off) = make_uint2(h0, h1);
            *(uint2*)(sm + KL_OFF + off) = make_uint2(lo0, lo1);
            split2(vv.x, vv.y, h0, lo0);
            split2(vv.z, vv.w, h1, lo1);
            *(uint2*)(sm + VH_OFF + off) = make_uint2(h0, h1);
            *(uint2*)(sm + VL_OFF + off) = make_uint2(lo0, lo1);
        }
        __syncthreads();

#pragma unroll
        for (int half = 0; half < 2; half++) {
            // ---- S = Q K^T over 64 kv cols: 8 n-tiles via 4 x4-loads ----
            float accS[8][4];
#pragma unroll
            for (int j = 0; j < 8; j++) {
                accS[j][0] = 0.f; accS[j][1] = 0.f;
                accS[j][2] = 0.f; accS[j][3] = 0.f;
            }
#pragma unroll
            for (int s = 0; s < 4; s++) {
                uint32_t qh[4], ql[4];
                uint32_t qoff = (arow * 72 + (uint32_t)(s * 16) + akoff) * 2;
                ldmx4(qh, sb + QH_OFF + qoff);
                ldmx4(ql, sb + QL_OFF + qoff);
#pragma unroll
                for (int jp = 0; jp < 4; jp++) {
                    uint32_t koff = ((uint32_t)(half * 64 + jp * 16) + k_r) * 144 +
                                    ((uint32_t)(s * 16) + k_c) * 2;
                    uint32_t kh4[4], kl4[4];
                    ldmx4(kh4, sb + KH_OFF + koff);
                    ldmx4(kl4, sb + KL_OFF + koff);
                    mma_bf16(accS[jp * 2],     qh, kh4);
                    mma_bf16(accS[jp * 2],     qh, kl4);
                    mma_bf16(accS[jp * 2],     ql, kh4);
                    mma_bf16(accS[jp * 2 + 1], qh, kh4 + 2);
                    mma_bf16(accS[jp * 2 + 1], qh, kl4 + 2);
                    mma_bf16(accS[jp * 2 + 1], ql, kh4 + 2);
                }
            }

            // ---- online softmax (rows g and g+8), exp on FMA pipe ----
            float mx0 = -1e30f, mx1 = -1e30f;
#pragma unroll
            for (int j = 0; j < 8; j++) {
                mx0 = fmaxf(mx0, fmaxf(accS[j][0], accS[j][1]));
                mx1 = fmaxf(mx1, fmaxf(accS[j][2], accS[j][3]));
            }
            mx0 = fmaxf(mx0, __shfl_xor_sync(0xffffffffu, mx0, 1));
            mx0 = fmaxf(mx0, __shfl_xor_sync(0xffffffffu, mx0, 2));
            mx1 = fmaxf(mx1, __shfl_xor_sync(0xffffffffu, mx1, 1));
            mx1 = fmaxf(mx1, __shfl_xor_sync(0xffffffffu, mx1, 2));
            float m0n = fmaxf(m0, mx0), m1n = fmaxf(m1, mx1);
            float al0 = fexp2((m0 - m0n) * L2E);
            float al1 = fexp2((m1 - m1n) * L2E);
            float rs0 = 0.f, rs1 = 0.f;
#pragma unroll
            for (int j = 0; j < 8; j++) {
                float p0 = fexp2((accS[j][0] - m0n) * L2E);
                float p1 = fexp2((accS[j][1] - m0n) * L2E);
                float p2 = fexp2((accS[j][2] - m1n) * L2E);
                float p3 = fexp2((accS[j][3] - m1n) * L2E);
                rs0 += p0 + p1; rs1 += p2 + p3;
                accS[j][0] = p0; accS[j][1] = p1;
                accS[j][2] = p2; accS[j][3] = p3;
            }
            rs0 += __shfl_xor_sync(0xffffffffu, rs0, 1);
            rs0 += __shfl_xor_sync(0xffffffffu, rs0, 2);
            rs1 += __shfl_xor_sync(0xffffffffu, rs1, 1);
            rs1 += __shfl_xor_sync(0xffffffffu, rs1, 2);
            l0 = l0 * al0 + rs0;
            l1 = l1 * al1 + rs1;
            m0 = m0n; m1 = m1n;
#pragma unroll
            for (int j = 0; j < 8; j++) {
                accO[j][0] *= al0; accO[j][1] *= al0;
                accO[j][2] *= al1; accO[j][3] *= al1;
            }

            // ---- O += P V : P A-frags built in-register from accS ----
#pragma unroll
            for (int s = 0; s < 4; s++) {
                uint32_t ph[4], pl[4];
                split2(accS[2 * s][0],     accS[2 * s][1],     ph[0], pl[0]);
                split2(accS[2 * s][2],     accS[2 * s][3],     ph[1], pl[1]);
                split2(accS[2 * s + 1][0], accS[2 * s + 1][1], ph[2], pl[2]);
                split2(accS[2 * s + 1][2], accS[2 * s + 1][3], ph[3], pl[3]);
                uint32_t vro = ((uint32_t)(half * 64 + s * 16) + v_r) * 144;
#pragma unroll
                for (int jp = 0; jp < 4; jp++) {
                    uint32_t voff = vro + (uint32_t)(jp * 32) + v_c;
                    uint32_t vh4[4], vl4[4];
                    ldmx4t(vh4, sb + VH_OFF + voff);
                    ldmx4t(vl4, sb + VL_OFF + voff);
                    mma_bf16(accO[jp * 2],     ph, vh4);
                    mma_bf16(accO[jp * 2],     ph, vl4);
                    mma_bf16(accO[jp * 2],     pl, vh4);
                    mma_bf16(accO[jp * 2 + 1], ph, vh4 + 2);
                    mma_bf16(accO[jp * 2 + 1], ph, vl4 + 2);
                    mma_bf16(accO[jp * 2 + 1], pl, vh4 + 2);
                }
            }
        }
        __syncthreads();   // protect K/V before next tile's overwrite
    }

    // ---- normalize and write AO ----
    const int b = bh / HC, h = bh % HC;
    const float inv0 = 1.0f / l0, inv1 = 1.0f / l1;
    const size_t base0 = (size_t)(b * LQC + q0 + w * 16 + g) * DIMC + h * 64;
    const size_t base1 = base0 + (size_t)8 * DIMC;
#pragma unroll
    for (int j = 0; j < 8; j++) {
        *(float2*)&gAO[base0 + j * 8 + qd * 2] =
            make_float2(accO[j][0] * inv0, accO[j][1] * inv0);
        *(float2*)&gAO[base1 + j * 8 + qd * 2] =
            make_float2(accO[j][2] * inv1, accO[j][3] * inv1);
    }
}

// =====================================================================
// launch
// =====================================================================
extern "C" void kernel_launch(void* const* d_in, const int* in_sizes, int n_in,
                              void* d_out, int out_size)
{
    const float* queries = (const float*)d_in[0];
    const float* context = (const float*)d_in[1];
    const float* qcos    = (const float*)d_in[2];
    const float* qsin    = (const float*)d_in[3];
    const float* kcos    = (const float*)d_in[4];
    const float* ksin    = (const float*)d_in[5];
    const float* Wq      = (const float*)d_in[6];
    const float* Wkv     = (const float*)d_in[7];
    const float* Wo      = (const float*)d_in[8];
    const float* qnw     = (const float*)d_in[9];
    const float* knw     = (const float*)d_in[10];
    float* out = (float*)d_out;

    float *pQ, *pK, *pV, *pAO;
    cudaGetSymbolAddress((void**)&pQ,  g_Q);
    cudaGetSymbolAddress((void**)&pK,  g_K);
    cudaGetSymbolAddress((void**)&pV,  g_V);
    cudaGetSymbolAddress((void**)&pAO, g_AO);

    cudaFuncSetAttribute(mma_gemm<0>, cudaFuncAttributeMaxDynamicSharedMemorySize, SMEM_MM);
    cudaFuncSetAttribute(mma_gemm<1>, cudaFuncAttributeMaxDynamicSharedMemorySize, SMEM_MM);
    cudaFuncSetAttribute(mma_gemm<2>, cudaFuncAttributeMaxDynamicSharedMemorySize, SMEM_MM);
    cudaFuncSetAttribute(flash_mma, cudaFuncAttributeMaxDynamicSharedMemorySize, FA_SMEM);

    dim3 blk(256);
    dim3 gg(NR / 128, HC);

    mma_gemm<1><<<gg, blk, SMEM_MM>>>(queries, Wq,  0,    qcos, qsin, qnw, pQ);
    mma_gemm<1><<<gg, blk, SMEM_MM>>>(context, Wkv, 0,    kcos, ksin, knw, pK);
    mma_gemm<0><<<gg, blk, SMEM_MM>>>(context, Wkv, DIMC,
                                      (const float*)0, (const float*)0,
                                      (const float*)0, pV);

    flash_mma<<<dim3(LQC / 128, BC * HC), blk, FA_SMEM>>>(pQ, pK, pV, pAO);

    mma_gemm<2><<<gg, blk, SMEM_MM>>>(pAO, Wo, 0,
                                      (const float*)0, (const float*)0,
                                      (const float*)0, out);
}